// round 9
// baseline (speedup 1.0000x reference)
#include <cuda_runtime.h>
#include <cuda_fp16.h>
#include <math.h>
#include <stdint.h>

#define T_TOK 1024
#define H_DIM 2048
#define I_DIM 768
#define E_NUM 32
#define K_TOP 8

#define BM 128
#define BN 64
#define BK 32            // k-floats per slab (fp16 row = 64B, fp32 row = 128B)
#define RSB 80           // fp16 smem row stride bytes (conflict-free ldmatrix)
#define STAGES 4

// per-stage layout: [A fp16 : BM*RSB][B fp32 raw rows : nB*128]
#define GU_A_BYTES (BM * RSB)                 // 10240
#define GU_B32     (2 * BN * 128)             // 16384 (gate rows 0..63, up rows 64..127)
#define STG_GU     (GU_A_BYTES + GU_B32)      // 26624
#define GU_DEST    (STAGES * STG_GU)          // fp16 B staging (2*BN rows * RSB)
#define GU_SMEM    (GU_DEST + 2 * BN * RSB)   // 116736

#define DN_A_BYTES (BM * RSB)                 // 10240
#define DN_B32     (BN * 128)                 // 8192
#define STG_DN     (DN_A_BYTES + DN_B32)      // 18432
#define DN_DEST    (STAGES * STG_DN)
#define DN_SMEM    (DN_DEST + BN * RSB)       // 78848

#define GU_NC (H_DIM / BK)                    // 64
#define DN_NC (I_DIM / BK)                    // 24

// ---------------- scratch ----------------
__device__ int    g_cnt[E_NUM];
__device__ int    g_off[E_NUM + 1];
__device__ int    g_list_tok[E_NUM * T_TOK];
__device__ float  g_list_w[E_NUM * T_TOK];
__device__ int    g_list_tk[E_NUM * T_TOK];
__device__ int    g_slot_of[T_TOK * K_TOP];
__device__ __half g_act[(size_t)T_TOK * K_TOP * I_DIM];
__device__ float  g_pair[(size_t)T_TOK * K_TOP * H_DIM];
__device__ __half g_xh[(size_t)T_TOK * H_DIM];

// ---------------- x fp32->fp16 + zero counters ----------------
__global__ void convert_x_kernel(const float* __restrict__ x) {
    if (blockIdx.x == 0 && threadIdx.x < E_NUM) g_cnt[threadIdx.x] = 0;
    const size_t NX = (size_t)T_TOK * H_DIM / 4;
    size_t stride = (size_t)gridDim.x * blockDim.x;
    for (size_t i = (size_t)blockIdx.x * blockDim.x + threadIdx.x; i < NX; i += stride) {
        float4 v = ((const float4*)x)[i];
        __half2 h[2];
        h[0] = __floats2half2_rn(v.x, v.y);
        h[1] = __floats2half2_rn(v.z, v.w);
        *(uint2*)(g_xh + i * 4) = *(uint2*)h;
    }
}

// ---------------- router ----------------
__global__ void router_kernel(const float* __restrict__ x,
                              const float* __restrict__ gate_w,
                              float* __restrict__ logits_out) {
    const int TPB = 4;
    __shared__ float xs[TPB][H_DIM];
    __shared__ float lg[TPB][E_NUM];

    int t0 = blockIdx.x * TPB;
    const float4* xv  = (const float4*)(x + (size_t)t0 * H_DIM);
    float4*       xsv = (float4*)&xs[0][0];
    for (int i = threadIdx.x; i < TPB * H_DIM / 4; i += blockDim.x) xsv[i] = xv[i];
    __syncthreads();

    int warp = threadIdx.x >> 5;
    int lane = threadIdx.x & 31;

    for (int sub = 0; sub < 4; sub++) {
        int e = warp + sub * 8;
        const float* w = gate_w + (size_t)e * H_DIM;
        float p0 = 0.f, p1 = 0.f, p2 = 0.f, p3 = 0.f;
        for (int h = lane; h < H_DIM; h += 32) {
            float wv = w[h];
            p0 += xs[0][h] * wv;
            p1 += xs[1][h] * wv;
            p2 += xs[2][h] * wv;
            p3 += xs[3][h] * wv;
        }
        for (int o = 16; o; o >>= 1) {
            p0 += __shfl_xor_sync(0xFFFFFFFFu, p0, o);
            p1 += __shfl_xor_sync(0xFFFFFFFFu, p1, o);
            p2 += __shfl_xor_sync(0xFFFFFFFFu, p2, o);
            p3 += __shfl_xor_sync(0xFFFFFFFFu, p3, o);
        }
        if (lane == 0) { lg[0][e] = p0; lg[1][e] = p1; lg[2][e] = p2; lg[3][e] = p3; }
    }
    __syncthreads();

    if (warp < TPB) {
        int t = t0 + warp;
        float logit = lg[warp][lane];
        if (logits_out) logits_out[(size_t)t * E_NUM + lane] = logit;

        float m = logit;
        for (int o = 16; o; o >>= 1) m = fmaxf(m, __shfl_xor_sync(0xFFFFFFFFu, m, o));
        float ex = expf(logit - m);
        float s = ex;
        for (int o = 16; o; o >>= 1) s += __shfl_xor_sync(0xFFFFFFFFu, s, o);
        float prob = ex / s;

        float v = prob;
        float wsum = 0.f;
        float selw[K_TOP];
        int   sele[K_TOP];
#pragma unroll
        for (int k = 0; k < K_TOP; k++) {
            float mv = v;
            for (int o = 16; o; o >>= 1) mv = fmaxf(mv, __shfl_xor_sync(0xFFFFFFFFu, mv, o));
            unsigned msk = __ballot_sync(0xFFFFFFFFu, v == mv);
            int src = __ffs(msk) - 1;
            if (lane == 0) { sele[k] = src; selw[k] = mv; wsum += mv; }
            if (lane == src) v = -1.f;
        }
        if (lane == 0) {
#pragma unroll
            for (int k = 0; k < K_TOP; k++) {
                int e = sele[k];
                float wn = selw[k] / wsum;
                int pos = atomicAdd(&g_cnt[e], 1);
                g_list_tok[e * T_TOK + pos] = t;
                g_list_w[e * T_TOK + pos]   = wn;
                g_list_tk[e * T_TOK + pos]  = t * K_TOP + k;
            }
        }
    }
}

// ---------------- fused scan + remap ----------------
__global__ void scan_remap_kernel() {
    if (threadIdx.x == 0) {
        int acc = 0;
        for (int e = 0; e < E_NUM; e++) { g_off[e] = acc; acc += g_cnt[e]; }
        g_off[E_NUM] = acc;
    }
    __syncthreads();
    for (int e = 0; e < E_NUM; e++) {
        int n = g_cnt[e], o = g_off[e];
        for (int p = threadIdx.x; p < n; p += blockDim.x)
            g_slot_of[g_list_tk[e * T_TOK + p]] = o + p;
    }
}

__device__ __forceinline__ float silu_f(float g) { return g / (1.f + expf(-g)); }

__device__ __forceinline__ uint32_t smem_u32(const void* p) {
    uint32_t a;
    asm("{ .reg .u64 t; cvta.to.shared.u64 t, %1; cvt.u32.u64 %0, t; }" : "=r"(a) : "l"(p));
    return a;
}

#define LDM4(r0, r1, r2, r3, addr) \
    asm volatile("ldmatrix.sync.aligned.m8n8.x4.shared.b16 {%0,%1,%2,%3}, [%4];" \
                 : "=r"(r0), "=r"(r1), "=r"(r2), "=r"(r3) : "r"(addr))

#define CP16(dst, src) \
    asm volatile("cp.async.cg.shared.global [%0], [%1], 16;" :: "r"(dst), "l"(src) : "memory")
#define CP_COMMIT() asm volatile("cp.async.commit_group;" ::: "memory")
#define CP_WAIT(n)  asm volatile("cp.async.wait_group %0;" :: "n"(n) : "memory")

__device__ __forceinline__ void mma_f16(float* c, uint32_t a0, uint32_t a1, uint32_t a2, uint32_t a3,
                                        uint32_t b0, uint32_t b1) {
    asm volatile("mma.sync.aligned.m16n8k16.row.col.f32.f16.f16.f32 "
                 "{%0,%1,%2,%3}, {%4,%5,%6,%7}, {%8,%9}, {%0,%1,%2,%3};"
                 : "+f"(c[0]), "+f"(c[1]), "+f"(c[2]), "+f"(c[3])
                 : "r"(a0), "r"(a1), "r"(a2), "r"(a3), "r"(b0), "r"(b1));
}

// convert one 16B fp32 chunk (4 floats) in stage to 8B fp16 in dest layout
__device__ __forceinline__ void cvt_chunk(unsigned char* dsm_p, uint32_t src_off,
                                          uint32_t dest_off, int c) {
    float4 v = *(const float4*)(dsm_p + src_off + c * 16);
    __half2 h[2];
    h[0] = __floats2half2_rn(v.x, v.y);
    h[1] = __floats2half2_rn(v.z, v.w);
    *(uint2*)(dsm_p + dest_off + (c >> 3) * RSB + (c & 7) * 8) = *(uint2*)h;
}

extern __shared__ unsigned char dsm[];

// ---------------- grouped gate+up GEMM (fp16 mma, fp32 weights via cp.async + smem cvt) --------
__global__ __launch_bounds__(256) void gateup_kernel(const float* __restrict__ gw,
                                                     const float* __restrict__ uw) {
    int e  = blockIdx.z;
    int n  = g_cnt[e];
    int m0 = blockIdx.x * BM;
    if (m0 >= n) return;
    int c0 = blockIdx.y * BN;

    uint32_t sbase = smem_u32(dsm);
    int tid  = threadIdx.x;
    int lane = tid & 31;
    int warp = tid >> 5;
    int wM = warp & 3;
    int wN = warp >> 2;

    // A loader: 2 threads per row (fp16 source), 32 B per slab per thread
    int lr = tid >> 1;
    int hf = tid & 1;
    int tokA = g_list_tok[e * T_TOK + min(m0 + lr, n - 1)];
    const __half* pA = g_xh + (size_t)tokA * H_DIM + hf * 16;
    uint32_t soA = lr * RSB + hf * 32;

    // B loader: fp32, thread owns 4 chunks (rows rb, rb+32, rb+64, rb+96)
    int rb = tid >> 3;            // 0..31
    int kq = (tid & 7) * 4;       // float offset in row
    const float* pBf[4];
    uint32_t soB[4];
#pragma unroll
    for (int i = 0; i < 4; i++) {
        int r = rb + 32 * i;      // 0..127: <64 gate, >=64 up
        const float* base = (r < 64)
            ? gw + ((size_t)e * I_DIM + (c0 + r)) * H_DIM
            : uw + ((size_t)e * I_DIM + (c0 + r - 64)) * H_DIM;
        pBf[i] = base + kq;
        soB[i] = GU_A_BYTES + r * 128 + (tid & 7) * 16;
    }

    // ldmatrix bases: A in stage (add stage offset), B in fixed fp16 dest
    int mat = lane >> 3, rr = lane & 7;
    uint32_t aBase[2], bgBase[2], buBase[2];
#pragma unroll
    for (int mi = 0; mi < 2; mi++)
        aBase[mi] = sbase + (uint32_t)((wM * 32 + mi * 16 + (mat & 1) * 8 + rr) * RSB + (mat >> 1) * 16);
#pragma unroll
    for (int p = 0; p < 2; p++) {
        uint32_t roff = (uint32_t)((wN * 32 + p * 16 + (mat >> 1) * 8 + rr) * RSB + (mat & 1) * 16);
        bgBase[p] = sbase + GU_DEST + roff;                  // gate rows 0..63
        buBase[p] = sbase + GU_DEST + 64 * RSB + roff;       // up rows 64..127
    }

    float cg[2][4][4] = {};
    float cu[2][4][4] = {};

#define GU_ISSUE(i)                                                       \
    { uint32_t bb = ((i) & (STAGES - 1)) * STG_GU;                        \
      const __half* sa = pA + (i) * 32;                                   \
      CP16(sbase + bb + soA, sa); CP16(sbase + bb + soA + 16, sa + 8);    \
      _Pragma("unroll")                                                   \
      for (int j = 0; j < 4; j++) CP16(sbase + bb + soB[j], pBf[j] + (i) * 32); }

    GU_ISSUE(0); CP_COMMIT();
    GU_ISSUE(1); CP_COMMIT();
    GU_ISSUE(2); CP_COMMIT();

    for (int i = 0; i < GU_NC; i++) {
        CP_WAIT(STAGES - 2);
        __syncthreads();
        uint32_t st = (i & (STAGES - 1)) * STG_GU;

        // convert B fp32 (stage) -> fp16 dest; chunks tid+256j give conflict-free LDS.128
#pragma unroll
        for (int j = 0; j < 4; j++) cvt_chunk(dsm, st + GU_A_BYTES, GU_DEST, tid + 256 * j);
        __syncthreads();

#pragma unroll
        for (int ks = 0; ks < 2; ks++) {
            uint32_t af[2][4];
#pragma unroll
            for (int mi = 0; mi < 2; mi++)
                LDM4(af[mi][0], af[mi][1], af[mi][2], af[mi][3], aBase[mi] + st + ks * 32);
            uint32_t gf[2][4], uf[2][4];
#pragma unroll
            for (int p = 0; p < 2; p++) {
                LDM4(gf[p][0], gf[p][1], gf[p][2], gf[p][3], bgBase[p] + ks * 32);
                LDM4(uf[p][0], uf[p][1], uf[p][2], uf[p][3], buBase[p] + ks * 32);
            }
#pragma unroll
            for (int t = 0; t < 4; t++) {
                int p = t >> 1, q = (t & 1) * 2;
#pragma unroll
                for (int mi = 0; mi < 2; mi++) {
                    mma_f16(cg[mi][t], af[mi][0], af[mi][1], af[mi][2], af[mi][3], gf[p][q], gf[p][q + 1]);
                    mma_f16(cu[mi][t], af[mi][0], af[mi][1], af[mi][2], af[mi][3], uf[p][q], uf[p][q + 1]);
                }
            }
        }
        // tail-safe unconditional commit
        if (i + STAGES - 1 < GU_NC) GU_ISSUE(i + STAGES - 1);
        CP_COMMIT();
    }
#undef GU_ISSUE

    // ---- epilogue ----
    int off = g_off[e];
    int g  = lane >> 2;
    int tq = lane & 3;
#pragma unroll
    for (int mi = 0; mi < 2; mi++) {
        int r0 = m0 + wM * 32 + mi * 16 + g;
        int r1 = r0 + 8;
        float w0 = (r0 < n) ? g_list_w[e * T_TOK + r0] : 0.f;
        float w1 = (r1 < n) ? g_list_w[e * T_TOK + r1] : 0.f;
#pragma unroll
        for (int t = 0; t < 4; t++) {
            int col = c0 + wN * 32 + t * 8 + 2 * tq;
            if (r0 < n) {
                float ox = silu_f(cg[mi][t][0]) * cu[mi][t][0] * w0;
                float oy = silu_f(cg[mi][t][1]) * cu[mi][t][1] * w0;
                *(__half2*)&g_act[((size_t)(off + r0)) * I_DIM + col] = __floats2half2_rn(ox, oy);
            }
            if (r1 < n) {
                float ox = silu_f(cg[mi][t][2]) * cu[mi][t][2] * w1;
                float oy = silu_f(cg[mi][t][3]) * cu[mi][t][3] * w1;
                *(__half2*)&g_act[((size_t)(off + r1)) * I_DIM + col] = __floats2half2_rn(ox, oy);
            }
        }
    }
}

// ---------------- grouped down GEMM (fp16 mma, fp32 weights via cp.async + smem cvt) ---------
__global__ __launch_bounds__(256) void down_kernel(const float* __restrict__ dw) {
    int e  = blockIdx.z;
    int n  = g_cnt[e];
    int m0 = blockIdx.x * BM;
    if (m0 >= n) return;
    int c0  = blockIdx.y * BN;
    int off = g_off[e];

    uint32_t sbase = smem_u32(dsm);
    int tid  = threadIdx.x;
    int lane = tid & 31;
    int warp = tid >> 5;
    int wM = warp & 3;
    int wN = warp >> 2;

    // A loader: fp16 g_act, 2 thr/row
    int lr = tid >> 1;
    int hf = tid & 1;
    const __half* pA = g_act + (size_t)(off + min(m0 + lr, n - 1)) * I_DIM + hf * 16;
    uint32_t soA = lr * RSB + hf * 32;

    // B loader: fp32 dw, thread owns 2 chunks (rows rb, rb+32)
    int rb = tid >> 3;
    int kq = (tid & 7) * 4;
    const float* pBf[2];
    uint32_t soB[2];
#pragma unroll
    for (int i = 0; i < 2; i++) {
        int r = rb + 32 * i;   // 0..63
        pBf[i] = dw + ((size_t)e * H_DIM + (c0 + r)) * I_DIM + kq;
        soB[i] = DN_A_BYTES + r * 128 + (tid & 7) * 16;
    }

    int mat = lane >> 3, rr = lane & 7;
    uint32_t aBase[2], bBase[2];
#pragma unroll
    for (int mi = 0; mi < 2; mi++)
        aBase[mi] = sbase + (uint32_t)((wM * 32 + mi * 16 + (mat & 1) * 8 + rr) * RSB + (mat >> 1) * 16);
#pragma unroll
    for (int p = 0; p < 2; p++)
        bBase[p] = sbase + DN_DEST + (uint32_t)((wN * 32 + p * 16 + (mat >> 1) * 8 + rr) * RSB + (mat & 1) * 16);

    float c[2][4][4] = {};

#define DN_ISSUE(i)                                                       \
    { uint32_t bb = ((i) & (STAGES - 1)) * STG_DN;                        \
      const __half* sa = pA + (i) * 32;                                   \
      CP16(sbase + bb + soA, sa); CP16(sbase + bb + soA + 16, sa + 8);    \
      _Pragma("unroll")                                                   \
      for (int j = 0; j < 2; j++) CP16(sbase + bb + soB[j], pBf[j] + (i) * 32); }

    DN_ISSUE(0); CP_COMMIT();
    DN_ISSUE(1); CP_COMMIT();
    DN_ISSUE(2); CP_COMMIT();

    for (int i = 0; i < DN_NC; i++) {
        CP_WAIT(STAGES - 2);
        __syncthreads();
        uint32_t st = (i & (STAGES - 1)) * STG_DN;

#pragma unroll
        for (int j = 0; j < 2; j++) cvt_chunk(dsm, st + DN_A_BYTES, DN_DEST, tid + 256 * j);
        __syncthreads();

#pragma unroll
        for (int ks = 0; ks < 2; ks++) {
            uint32_t af[2][4];
#pragma unroll
            for (int mi = 0; mi < 2; mi++)
                LDM4(af[mi][0], af[mi][1], af[mi][2], af[mi][3], aBase[mi] + st + ks * 32);
            uint32_t bf[2][4];
#pragma unroll
            for (int p = 0; p < 2; p++)
                LDM4(bf[p][0], bf[p][1], bf[p][2], bf[p][3], bBase[p] + ks * 32);
#pragma unroll
            for (int t = 0; t < 4; t++) {
                int p = t >> 1, q = (t & 1) * 2;
#pragma unroll
                for (int mi = 0; mi < 2; mi++)
                    mma_f16(c[mi][t], af[mi][0], af[mi][1], af[mi][2], af[mi][3], bf[p][q], bf[p][q + 1]);
            }
        }
        if (i + STAGES - 1 < DN_NC) DN_ISSUE(i + STAGES - 1);
        CP_COMMIT();
    }
#undef DN_ISSUE

    int g  = lane >> 2;
    int tq = lane & 3;
#pragma unroll
    for (int mi = 0; mi < 2; mi++) {
        int r0 = m0 + wM * 32 + mi * 16 + g;
        int r1 = r0 + 8;
#pragma unroll
        for (int t = 0; t < 4; t++) {
            int col = c0 + wN * 32 + t * 8 + 2 * tq;
            if (r0 < n) {
                float2 o = make_float2(c[mi][t][0], c[mi][t][1]);
                *(float2*)&g_pair[((size_t)(off + r0)) * H_DIM + col] = o;
            }
            if (r1 < n) {
                float2 o = make_float2(c[mi][t][2], c[mi][t][3]);
                *(float2*)&g_pair[((size_t)(off + r1)) * H_DIM + col] = o;
            }
        }
    }
}

// ---------------- per-token reduction ----------------
__global__ void reduce_kernel(float* __restrict__ out) {
    int t = blockIdx.x;
    int s[K_TOP];
#pragma unroll
    for (int k = 0; k < K_TOP; k++) s[k] = g_slot_of[t * K_TOP + k];
    const float4* base = (const float4*)g_pair;
    float4* ob = (float4*)(out + (size_t)t * H_DIM);
    for (int i = threadIdx.x; i < H_DIM / 4; i += blockDim.x) {
        float4 acc = make_float4(0.f, 0.f, 0.f, 0.f);
#pragma unroll
        for (int k = 0; k < K_TOP; k++) {
            float4 v = base[(size_t)s[k] * (H_DIM / 4) + i];
            acc.x += v.x; acc.y += v.y; acc.z += v.z; acc.w += v.w;
        }
        ob[i] = acc;
    }
}

// ---------------- launch ----------------
extern "C" void kernel_launch(void* const* d_in, const int* in_sizes, int n_in,
                              void* d_out, int out_size) {
    const float* x      = (const float*)d_in[0];
    const float* gate_w = (const float*)d_in[1];
    const float* gw     = (const float*)d_in[2];
    const float* uw     = (const float*)d_in[3];
    const float* dw     = (const float*)d_in[4];
    float* out = (float*)d_out;

    float* logits = (out_size >= T_TOK * H_DIM + T_TOK * E_NUM) ? (out + (size_t)T_TOK * H_DIM)
                                                                : (float*)0;

    cudaFuncSetAttribute(gateup_kernel, cudaFuncAttributeMaxDynamicSharedMemorySize, GU_SMEM);
    cudaFuncSetAttribute(down_kernel,   cudaFuncAttributeMaxDynamicSharedMemorySize, DN_SMEM);

    convert_x_kernel<<<256, 256>>>(x);
    router_kernel<<<T_TOK / 4, 256>>>(x, gate_w, logits);
    scan_remap_kernel<<<1, 256>>>();
    gateup_kernel<<<dim3(T_TOK / BM, I_DIM / BN, E_NUM), 256, GU_SMEM>>>(gw, uw);
    down_kernel<<<dim3(T_TOK / BM, H_DIM / BN, E_NUM), 256, DN_SMEM>>>(dw);
    reduce_kernel<<<T_TOK, 256>>>(out);
}

// round 10
// speedup vs baseline: 1.1206x; 1.1206x over previous
#include <cuda_runtime.h>
#include <cuda_fp16.h>
#include <math.h>
#include <stdint.h>

#define T_TOK 1024
#define H_DIM 2048
#define I_DIM 768
#define E_NUM 32
#define K_TOP 8

#define BM 128
#define BN 64
#define BK 32            // k-floats per slab (fp16 row = 64B, fp32 row = 128B)
#define RSB 80           // fp16 smem row stride bytes (conflict-free ldmatrix)
#define STAGES 3

// per-stage layout: [A fp16 : BM*RSB][B fp32 raw rows : nB*128]
#define GU_A_BYTES (BM * RSB)                 // 10240
#define GU_B32     (2 * BN * 128)             // 16384
#define STG_GU     (GU_A_BYTES + GU_B32)      // 26624
#define GU_DEST    (STAGES * STG_GU)          // fp16 B staging
#define GU_SMEM    (GU_DEST + 2 * BN * RSB)   // 90112  -> 2 CTAs/SM

#define DN_A_BYTES (BM * RSB)
#define DN_B32     (BN * 128)
#define STG_DN     (DN_A_BYTES + DN_B32)      // 18432
#define DN_DEST    (STAGES * STG_DN)
#define DN_SMEM    (DN_DEST + BN * RSB)       // 60416  -> 2 CTAs/SM

#define GU_NC (H_DIM / BK)                    // 64
#define DN_NC (I_DIM / BK)                    // 24

// ---------------- scratch ----------------
__device__ int    g_cnt[E_NUM];
__device__ int    g_off[E_NUM + 1];
__device__ int    g_list_tok[E_NUM * T_TOK];
__device__ float  g_list_w[E_NUM * T_TOK];
__device__ int    g_list_tk[E_NUM * T_TOK];
__device__ int    g_slot_of[T_TOK * K_TOP];
__device__ __half g_act[(size_t)T_TOK * K_TOP * I_DIM];
__device__ float  g_pair[(size_t)T_TOK * K_TOP * H_DIM];
__device__ __half g_xh[(size_t)T_TOK * H_DIM];

// ---------------- x fp32->fp16 + zero counters ----------------
__global__ void convert_x_kernel(const float* __restrict__ x) {
    if (blockIdx.x == 0 && threadIdx.x < E_NUM) g_cnt[threadIdx.x] = 0;
    const size_t NX = (size_t)T_TOK * H_DIM / 4;
    size_t stride = (size_t)gridDim.x * blockDim.x;
    for (size_t i = (size_t)blockIdx.x * blockDim.x + threadIdx.x; i < NX; i += stride) {
        float4 v = ((const float4*)x)[i];
        __half2 h[2];
        h[0] = __floats2half2_rn(v.x, v.y);
        h[1] = __floats2half2_rn(v.z, v.w);
        *(uint2*)(g_xh + i * 4) = *(uint2*)h;
    }
}

// ---------------- router ----------------
__global__ void router_kernel(const float* __restrict__ x,
                              const float* __restrict__ gate_w,
                              float* __restrict__ logits_out) {
    const int TPB = 4;
    __shared__ float xs[TPB][H_DIM];
    __shared__ float lg[TPB][E_NUM];

    int t0 = blockIdx.x * TPB;
    const float4* xv  = (const float4*)(x + (size_t)t0 * H_DIM);
    float4*       xsv = (float4*)&xs[0][0];
    for (int i = threadIdx.x; i < TPB * H_DIM / 4; i += blockDim.x) xsv[i] = xv[i];
    __syncthreads();

    int warp = threadIdx.x >> 5;
    int lane = threadIdx.x & 31;

    for (int sub = 0; sub < 4; sub++) {
        int e = warp + sub * 8;
        const float* w = gate_w + (size_t)e * H_DIM;
        float p0 = 0.f, p1 = 0.f, p2 = 0.f, p3 = 0.f;
        for (int h = lane; h < H_DIM; h += 32) {
            float wv = w[h];
            p0 += xs[0][h] * wv;
            p1 += xs[1][h] * wv;
            p2 += xs[2][h] * wv;
            p3 += xs[3][h] * wv;
        }
        for (int o = 16; o; o >>= 1) {
            p0 += __shfl_xor_sync(0xFFFFFFFFu, p0, o);
            p1 += __shfl_xor_sync(0xFFFFFFFFu, p1, o);
            p2 += __shfl_xor_sync(0xFFFFFFFFu, p2, o);
            p3 += __shfl_xor_sync(0xFFFFFFFFu, p3, o);
        }
        if (lane == 0) { lg[0][e] = p0; lg[1][e] = p1; lg[2][e] = p2; lg[3][e] = p3; }
    }
    __syncthreads();

    if (warp < TPB) {
        int t = t0 + warp;
        float logit = lg[warp][lane];
        if (logits_out) logits_out[(size_t)t * E_NUM + lane] = logit;

        float m = logit;
        for (int o = 16; o; o >>= 1) m = fmaxf(m, __shfl_xor_sync(0xFFFFFFFFu, m, o));
        float ex = expf(logit - m);
        float s = ex;
        for (int o = 16; o; o >>= 1) s += __shfl_xor_sync(0xFFFFFFFFu, s, o);
        float prob = ex / s;

        float v = prob;
        float wsum = 0.f;
        float selw[K_TOP];
        int   sele[K_TOP];
#pragma unroll
        for (int k = 0; k < K_TOP; k++) {
            float mv = v;
            for (int o = 16; o; o >>= 1) mv = fmaxf(mv, __shfl_xor_sync(0xFFFFFFFFu, mv, o));
            unsigned msk = __ballot_sync(0xFFFFFFFFu, v == mv);
            int src = __ffs(msk) - 1;
            if (lane == 0) { sele[k] = src; selw[k] = mv; wsum += mv; }
            if (lane == src) v = -1.f;
        }
        if (lane == 0) {
#pragma unroll
            for (int k = 0; k < K_TOP; k++) {
                int e = sele[k];
                float wn = selw[k] / wsum;
                int pos = atomicAdd(&g_cnt[e], 1);
                g_list_tok[e * T_TOK + pos] = t;
                g_list_w[e * T_TOK + pos]   = wn;
                g_list_tk[e * T_TOK + pos]  = t * K_TOP + k;
            }
        }
    }
}

// ---------------- fused scan + remap ----------------
__global__ void scan_remap_kernel() {
    if (threadIdx.x == 0) {
        int acc = 0;
        for (int e = 0; e < E_NUM; e++) { g_off[e] = acc; acc += g_cnt[e]; }
        g_off[E_NUM] = acc;
    }
    __syncthreads();
    for (int e = 0; e < E_NUM; e++) {
        int n = g_cnt[e], o = g_off[e];
        for (int p = threadIdx.x; p < n; p += blockDim.x)
            g_slot_of[g_list_tk[e * T_TOK + p]] = o + p;
    }
}

__device__ __forceinline__ float silu_f(float g) { return g / (1.f + expf(-g)); }

__device__ __forceinline__ uint32_t smem_u32(const void* p) {
    uint32_t a;
    asm("{ .reg .u64 t; cvta.to.shared.u64 t, %1; cvt.u32.u64 %0, t; }" : "=r"(a) : "l"(p));
    return a;
}

#define LDM4(r0, r1, r2, r3, addr) \
    asm volatile("ldmatrix.sync.aligned.m8n8.x4.shared.b16 {%0,%1,%2,%3}, [%4];" \
                 : "=r"(r0), "=r"(r1), "=r"(r2), "=r"(r3) : "r"(addr))

#define CP16(dst, src) \
    asm volatile("cp.async.cg.shared.global [%0], [%1], 16;" :: "r"(dst), "l"(src) : "memory")
#define CP_COMMIT() asm volatile("cp.async.commit_group;" ::: "memory")
#define CP_WAIT(n)  asm volatile("cp.async.wait_group %0;" :: "n"(n) : "memory")

__device__ __forceinline__ void mma_f16(float* c, uint32_t a0, uint32_t a1, uint32_t a2, uint32_t a3,
                                        uint32_t b0, uint32_t b1) {
    asm volatile("mma.sync.aligned.m16n8k16.row.col.f32.f16.f16.f32 "
                 "{%0,%1,%2,%3}, {%4,%5,%6,%7}, {%8,%9}, {%0,%1,%2,%3};"
                 : "+f"(c[0]), "+f"(c[1]), "+f"(c[2]), "+f"(c[3])
                 : "r"(a0), "r"(a1), "r"(a2), "r"(a3), "r"(b0), "r"(b1));
}

// convert one 32B fp32 chunk (8 floats) in stage -> 16B fp16 in dest layout
// (2x LDS.128 + 1x STS.128). Dest mapping matches ldmatrix RSB=80 rows.
__device__ __forceinline__ void cvt32(unsigned char* dsm_p, uint32_t src_off,
                                      uint32_t dest_off, int c) {
    float4 v0 = *(const float4*)(dsm_p + src_off + c * 32);
    float4 v1 = *(const float4*)(dsm_p + src_off + c * 32 + 16);
    __half2 h[4];
    h[0] = __floats2half2_rn(v0.x, v0.y);
    h[1] = __floats2half2_rn(v0.z, v0.w);
    h[2] = __floats2half2_rn(v1.x, v1.y);
    h[3] = __floats2half2_rn(v1.z, v1.w);
    *(uint4*)(dsm_p + dest_off + (c >> 2) * RSB + (c & 3) * 16) = *(uint4*)h;
}

extern __shared__ unsigned char dsm[];

// ---------------- grouped gate+up GEMM (fp16 mma, fp32 weights, 3-stage, 2 CTAs/SM) ----------
__global__ __launch_bounds__(256, 2) void gateup_kernel(const float* __restrict__ gw,
                                                        const float* __restrict__ uw) {
    int e  = blockIdx.z;
    int n  = g_cnt[e];
    int m0 = blockIdx.x * BM;
    if (m0 >= n) return;
    int c0 = blockIdx.y * BN;

    uint32_t sbase = smem_u32(dsm);
    int tid  = threadIdx.x;
    int lane = tid & 31;
    int warp = tid >> 5;
    int wM = warp & 3;
    int wN = warp >> 2;

    // A loader: 2 threads per row (fp16 source), 32 B per slab per thread
    int lr = tid >> 1;
    int hf = tid & 1;
    int tokA = g_list_tok[e * T_TOK + min(m0 + lr, n - 1)];
    const __half* pA = g_xh + (size_t)tokA * H_DIM + hf * 16;
    uint32_t soA = lr * RSB + hf * 32;

    // B loader: fp32, thread owns 4 chunks (rows rb, rb+32, rb+64, rb+96)
    int rb = tid >> 3;
    int kq = (tid & 7) * 4;
    const float* pBf[4];
    uint32_t soB[4];
#pragma unroll
    for (int i = 0; i < 4; i++) {
        int r = rb + 32 * i;      // <64 gate, >=64 up
        const float* base = (r < 64)
            ? gw + ((size_t)e * I_DIM + (c0 + r)) * H_DIM
            : uw + ((size_t)e * I_DIM + (c0 + r - 64)) * H_DIM;
        pBf[i] = base + kq;
        soB[i] = GU_A_BYTES + r * 128 + (tid & 7) * 16;
    }

    int mat = lane >> 3, rr = lane & 7;
    uint32_t aBase[2], bgBase[2], buBase[2];
#pragma unroll
    for (int mi = 0; mi < 2; mi++)
        aBase[mi] = sbase + (uint32_t)((wM * 32 + mi * 16 + (mat & 1) * 8 + rr) * RSB + (mat >> 1) * 16);
#pragma unroll
    for (int p = 0; p < 2; p++) {
        uint32_t roff = (uint32_t)((wN * 32 + p * 16 + (mat >> 1) * 8 + rr) * RSB + (mat & 1) * 16);
        bgBase[p] = sbase + GU_DEST + roff;
        buBase[p] = sbase + GU_DEST + 64 * RSB + roff;
    }

    float cg[2][4][4] = {};
    float cu[2][4][4] = {};

#define GU_ISSUE(i)                                                       \
    { uint32_t bb = ((i) % STAGES) * STG_GU;                              \
      const __half* sa = pA + (i) * 32;                                   \
      CP16(sbase + bb + soA, sa); CP16(sbase + bb + soA + 16, sa + 8);    \
      _Pragma("unroll")                                                   \
      for (int j = 0; j < 4; j++) CP16(sbase + bb + soB[j], pBf[j] + (i) * 32); }

    GU_ISSUE(0); CP_COMMIT();
    GU_ISSUE(1); CP_COMMIT();

    for (int i = 0; i < GU_NC; i++) {
        CP_WAIT(STAGES - 2);      // commit-per-iter: pending <=1 -> stage i complete
        __syncthreads();
        uint32_t st = (i % STAGES) * STG_GU;

        // B fp32 -> fp16 dest (512 x 32B chunks)
#pragma unroll
        for (int j = 0; j < 2; j++) cvt32(dsm, st + GU_A_BYTES, GU_DEST, tid + 256 * j);
        __syncthreads();

#pragma unroll
        for (int ks = 0; ks < 2; ks++) {
            uint32_t af[2][4];
#pragma unroll
            for (int mi = 0; mi < 2; mi++)
                LDM4(af[mi][0], af[mi][1], af[mi][2], af[mi][3], aBase[mi] + st + ks * 32);
            uint32_t gf[2][4], uf[2][4];
#pragma unroll
            for (int p = 0; p < 2; p++) {
                LDM4(gf[p][0], gf[p][1], gf[p][2], gf[p][3], bgBase[p] + ks * 32);
                LDM4(uf[p][0], uf[p][1], uf[p][2], uf[p][3], buBase[p] + ks * 32);
            }
#pragma unroll
            for (int t = 0; t < 4; t++) {
                int p = t >> 1, q = (t & 1) * 2;
#pragma unroll
                for (int mi = 0; mi < 2; mi++) {
                    mma_f16(cg[mi][t], af[mi][0], af[mi][1], af[mi][2], af[mi][3], gf[p][q], gf[p][q + 1]);
                    mma_f16(cu[mi][t], af[mi][0], af[mi][1], af[mi][2], af[mi][3], uf[p][q], uf[p][q + 1]);
                }
            }
        }
        if (i + STAGES - 1 < GU_NC) GU_ISSUE(i + STAGES - 1);
        CP_COMMIT();
    }
#undef GU_ISSUE

    // ---- epilogue ----
    int off = g_off[e];
    int g  = lane >> 2;
    int tq = lane & 3;
#pragma unroll
    for (int mi = 0; mi < 2; mi++) {
        int r0 = m0 + wM * 32 + mi * 16 + g;
        int r1 = r0 + 8;
        float w0 = (r0 < n) ? g_list_w[e * T_TOK + r0] : 0.f;
        float w1 = (r1 < n) ? g_list_w[e * T_TOK + r1] : 0.f;
#pragma unroll
        for (int t = 0; t < 4; t++) {
            int col = c0 + wN * 32 + t * 8 + 2 * tq;
            if (r0 < n) {
                float ox = silu_f(cg[mi][t][0]) * cu[mi][t][0] * w0;
                float oy = silu_f(cg[mi][t][1]) * cu[mi][t][1] * w0;
                *(__half2*)&g_act[((size_t)(off + r0)) * I_DIM + col] = __floats2half2_rn(ox, oy);
            }
            if (r1 < n) {
                float ox = silu_f(cg[mi][t][2]) * cu[mi][t][2] * w1;
                float oy = silu_f(cg[mi][t][3]) * cu[mi][t][3] * w1;
                *(__half2*)&g_act[((size_t)(off + r1)) * I_DIM + col] = __floats2half2_rn(ox, oy);
            }
        }
    }
}

// ---------------- grouped down GEMM (fp16 mma, fp32 weights, 3-stage, 2 CTAs/SM) ------------
__global__ __launch_bounds__(256, 2) void down_kernel(const float* __restrict__ dw) {
    int e  = blockIdx.z;
    int n  = g_cnt[e];
    int m0 = blockIdx.x * BM;
    if (m0 >= n) return;
    int c0  = blockIdx.y * BN;
    int off = g_off[e];

    uint32_t sbase = smem_u32(dsm);
    int tid  = threadIdx.x;
    int lane = tid & 31;
    int warp = tid >> 5;
    int wM = warp & 3;
    int wN = warp >> 2;

    int lr = tid >> 1;
    int hf = tid & 1;
    const __half* pA = g_act + (size_t)(off + min(m0 + lr, n - 1)) * I_DIM + hf * 16;
    uint32_t soA = lr * RSB + hf * 32;

    int rb = tid >> 3;
    int kq = (tid & 7) * 4;
    const float* pBf[2];
    uint32_t soB[2];
#pragma unroll
    for (int i = 0; i < 2; i++) {
        int r = rb + 32 * i;
        pBf[i] = dw + ((size_t)e * H_DIM + (c0 + r)) * I_DIM + kq;
        soB[i] = DN_A_BYTES + r * 128 + (tid & 7) * 16;
    }

    int mat = lane >> 3, rr = lane & 7;
    uint32_t aBase[2], bBase[2];
#pragma unroll
    for (int mi = 0; mi < 2; mi++)
        aBase[mi] = sbase + (uint32_t)((wM * 32 + mi * 16 + (mat & 1) * 8 + rr) * RSB + (mat >> 1) * 16);
#pragma unroll
    for (int p = 0; p < 2; p++)
        bBase[p] = sbase + DN_DEST + (uint32_t)((wN * 32 + p * 16 + (mat >> 1) * 8 + rr) * RSB + (mat & 1) * 16);

    float c[2][4][4] = {};

#define DN_ISSUE(i)                                                       \
    { uint32_t bb = ((i) % STAGES) * STG_DN;                              \
      const __half* sa = pA + (i) * 32;                                   \
      CP16(sbase + bb + soA, sa); CP16(sbase + bb + soA + 16, sa + 8);    \
      _Pragma("unroll")                                                   \
      for (int j = 0; j < 2; j++) CP16(sbase + bb + soB[j], pBf[j] + (i) * 32); }

    DN_ISSUE(0); CP_COMMIT();
    DN_ISSUE(1); CP_COMMIT();

    for (int i = 0; i < DN_NC; i++) {
        CP_WAIT(STAGES - 2);
        __syncthreads();
        uint32_t st = (i % STAGES) * STG_DN;

        cvt32(dsm, st + DN_A_BYTES, DN_DEST, tid);   // 256 x 32B chunks
        __syncthreads();

#pragma unroll
        for (int ks = 0; ks < 2; ks++) {
            uint32_t af[2][4];
#pragma unroll
            for (int mi = 0; mi < 2; mi++)
                LDM4(af[mi][0], af[mi][1], af[mi][2], af[mi][3], aBase[mi] + st + ks * 32);
            uint32_t bf[2][4];
#pragma unroll
            for (int p = 0; p < 2; p++)
                LDM4(bf[p][0], bf[p][1], bf[p][2], bf[p][3], bBase[p] + ks * 32);
#pragma unroll
            for (int t = 0; t < 4; t++) {
                int p = t >> 1, q = (t & 1) * 2;
#pragma unroll
                for (int mi = 0; mi < 2; mi++)
                    mma_f16(c[mi][t], af[mi][0], af[mi][1], af[mi][2], af[mi][3], bf[p][q], bf[p][q + 1]);
            }
        }
        if (i + STAGES - 1 < DN_NC) DN_ISSUE(i + STAGES - 1);
        CP_COMMIT();
    }
#undef DN_ISSUE

    int g  = lane >> 2;
    int tq = lane & 3;
#pragma unroll
    for (int mi = 0; mi < 2; mi++) {
        int r0 = m0 + wM * 32 + mi * 16 + g;
        int r1 = r0 + 8;
#pragma unroll
        for (int t = 0; t < 4; t++) {
            int col = c0 + wN * 32 + t * 8 + 2 * tq;
            if (r0 < n) {
                float2 o = make_float2(c[mi][t][0], c[mi][t][1]);
                *(float2*)&g_pair[((size_t)(off + r0)) * H_DIM + col] = o;
            }
            if (r1 < n) {
                float2 o = make_float2(c[mi][t][2], c[mi][t][3]);
                *(float2*)&g_pair[((size_t)(off + r1)) * H_DIM + col] = o;
            }
        }
    }
}

// ---------------- per-token reduction ----------------
__global__ void reduce_kernel(float* __restrict__ out) {
    int t = blockIdx.x;
    int s[K_TOP];
#pragma unroll
    for (int k = 0; k < K_TOP; k++) s[k] = g_slot_of[t * K_TOP + k];
    const float4* base = (const float4*)g_pair;
    float4* ob = (float4*)(out + (size_t)t * H_DIM);
    for (int i = threadIdx.x; i < H_DIM / 4; i += blockDim.x) {
        float4 acc = make_float4(0.f, 0.f, 0.f, 0.f);
#pragma unroll
        for (int k = 0; k < K_TOP; k++) {
            float4 v = base[(size_t)s[k] * (H_DIM / 4) + i];
            acc.x += v.x; acc.y += v.y; acc.z += v.z; acc.w += v.w;
        }
        ob[i] = acc;
    }
}

// ---------------- launch ----------------
extern "C" void kernel_launch(void* const* d_in, const int* in_sizes, int n_in,
                              void* d_out, int out_size) {
    const float* x      = (const float*)d_in[0];
    const float* gate_w = (const float*)d_in[1];
    const float* gw     = (const float*)d_in[2];
    const float* uw     = (const float*)d_in[3];
    const float* dw     = (const float*)d_in[4];
    float* out = (float*)d_out;

    float* logits = (out_size >= T_TOK * H_DIM + T_TOK * E_NUM) ? (out + (size_t)T_TOK * H_DIM)
                                                                : (float*)0;

    cudaFuncSetAttribute(gateup_kernel, cudaFuncAttributeMaxDynamicSharedMemorySize, GU_SMEM);
    cudaFuncSetAttribute(down_kernel,   cudaFuncAttributeMaxDynamicSharedMemorySize, DN_SMEM);

    convert_x_kernel<<<256, 256>>>(x);
    router_kernel<<<T_TOK / 4, 256>>>(x, gate_w, logits);
    scan_remap_kernel<<<1, 256>>>();
    gateup_kernel<<<dim3(T_TOK / BM, I_DIM / BN, E_NUM), 256, GU_SMEM>>>(gw, uw);
    down_kernel<<<dim3(T_TOK / BM, H_DIM / BN, E_NUM), 256, DN_SMEM>>>(dw);
    reduce_kernel<<<T_TOK, 256>>>(out);
}